// round 17
// baseline (speedup 1.0000x reference)
#include <cuda_runtime.h>

#define BATCH 4
#define HH 128
#define WW 128
#define CIN 64
#define CQK 8
#define NPX 8          // pixels per attn block (consecutive x)
#define PLANE (HH*WW)
#define VSTRIDE 1664   // per-pixel v region: 13 x 128-float m-pair blocks
#define ADSTRIDE 52    // duplicated attn row stride (floats), 16B-aligned
#define ADPIX (25*ADSTRIDE)   // 1300 floats per pixel (dup attn)
#define SM_K 13312     // k_sm base (floats)
#define SM_T 14912     // att/halo/partial union base (floats)
#define SMEM_FLOATS 25312     // 101248 bytes

// ---------------- scratch (device globals, no runtime alloc) ----------------
__device__ float g_q[BATCH*CQK*PLANE];              //   2 MB
__device__ float g_k[BATCH*CQK*PLANE];              //   2 MB
__device__ float g_v[BATCH*CIN*PLANE];              //  16.8 MB
__device__ float g_partial[(long)BATCH*2048*3840];  // 125.8 MB fold partials

// ---------------- f32x2 packed helpers ----------------
__device__ __forceinline__ unsigned long long pk2(float a, float b) {
    unsigned long long r;
    asm("mov.b64 %0, {%1,%2};" : "=l"(r) : "f"(a), "f"(b));
    return r;
}
__device__ __forceinline__ void fma2(unsigned long long& acc,
                                     unsigned long long a, unsigned long long b) {
    asm("fma.rn.f32x2 %0, %1, %2, %0;" : "+l"(acc) : "l"(a), "l"(b));
}

// =====================================================================
// Kernel A: 1x1-conv projections q,k,v  (NHWC input -> NCHW scratch)
// block = two image rows (256 threads); float4 weight loads  [proven]
// =====================================================================
__global__ void __launch_bounds__(256) proj_kernel(
                            const float* __restrict__ x,
                            const float* __restrict__ Wq, const float* __restrict__ bq,
                            const float* __restrict__ Wk, const float* __restrict__ bk,
                            const float* __restrict__ Wv, const float* __restrict__ bv)
{
    __shared__ float s_wq[512], s_wk[512], s_wv[4096], s_bq[8], s_bk[8], s_bv[64];
    int tid = threadIdx.x;
    for (int i = tid; i < 512; i += 256) { s_wq[i] = Wq[i]; s_wk[i] = Wk[i]; }
    for (int i = tid; i < 4096; i += 256) s_wv[i] = Wv[i];
    if (tid < 8)  { s_bq[tid] = bq[tid]; s_bk[tid] = bk[tid]; }
    if (tid < 64) { s_bv[tid] = bv[tid]; }
    __syncthreads();

    int rowpair = blockIdx.x;            // 0..255
    int b = rowpair >> 6;
    int y = ((rowpair & 63) << 1) | (tid >> 7);
    int xcol = tid & 127;
    long pix = ((long)(b*HH + y))*WW + xcol;

    float4 xv[16];
    const float4* xp = (const float4*)(x + pix*64);
#pragma unroll
    for (int c4 = 0; c4 < 16; c4++) xv[c4] = xp[c4];

    int base_qk = (b*CQK)*PLANE + y*WW + xcol;
#pragma unroll 1
    for (int o = 0; o < 8; o++) {
        float aq = s_bq[o], ak = s_bk[o];
        const float4* wq4 = (const float4*)(s_wq + o*64);
        const float4* wk4 = (const float4*)(s_wk + o*64);
#pragma unroll
        for (int c4 = 0; c4 < 16; c4++) {
            float4 wq = wq4[c4], wk = wk4[c4], xc = xv[c4];
            aq += xc.x*wq.x + xc.y*wq.y + xc.z*wq.z + xc.w*wq.w;
            ak += xc.x*wk.x + xc.y*wk.y + xc.z*wk.z + xc.w*wk.w;
        }
        g_q[base_qk + o*PLANE] = aq;
        g_k[base_qk + o*PLANE] = ak;
    }
    int base_v = (b*CIN)*PLANE + y*WW + xcol;
#pragma unroll 1
    for (int o = 0; o < 64; o++) {
        float av = s_bv[o];
        const float4* wv4 = (const float4*)(s_wv + o*64);
#pragma unroll
        for (int c4 = 0; c4 < 16; c4++) {
            float4 wv = wv4[c4], xc = xv[c4];
            av += xc.x*wv.x + xc.y*wv.y + xc.z*wv.z + xc.w*wv.w;
        }
        g_v[base_v + o*PLANE] = av;
    }
}

// =====================================================================
// Kernel B: attention + block-level fold pre-reduction
// block = 8 pixels, 256 threads, warp w = pixel w. 2 blocks/SM.
// smem (floats, total 25312 = 101248 B):
//   [0, 13312)      s_vp: per-pixel v, stride VSTRIDE, m-pair interleaved:
//                   perm(f)=(m>>1)*128+(m&1)*2+(cc>>1)*4+(cc&1); REUSED as chunk
//   [13312, 14912)  k_sm: per-pixel compact k rows [25][8]
//   [14912, 25312)  union T (10400):
//      phase 1: v halo [64][5][12] @T+0, q halo @T+3840, k halo @T+4320
//      phase 2: att DUPLICATED [8 px][25 rows][52] ({a,a} pairs)
//      phase 3: s_partial[5][12][64] (3840)
// =====================================================================
__global__ void __launch_bounds__(256, 2) attn_kernel(float* __restrict__ attn_out)
{
    extern __shared__ float sm[];
    float* s_vp  = sm;
    float* s_k   = sm + SM_K;
    float* s_T   = sm + SM_T;
    float* s_vt  = s_T;
    float* s_qt  = s_T + 3840;
    float* s_kt  = s_T + 4320;
    float* s_att = s_T;          // overlay after halo phase (duplicated pairs)
    float* s_partial = s_T;      // overlay after attn reads done

    int tid = threadIdx.x;
    int wid = tid >> 5;
    int l   = tid & 31;
    int b  = blockIdx.x >> 11;
    int r  = blockIdx.x & 2047;
    int y  = r >> 4;
    int x0 = (r & 15) * NPX;
    int p  = wid;

    // ---- P0: stage halo tiles (zero-padded like unfold) ----
    for (int idx = tid; idx < 480; idx += 256) {
        int c = idx/60, r2 = idx%60, dy = r2/12, xx = r2%12;
        int gy = y + dy - 2, gx = x0 + xx - 2;
        float vq = 0.f, vk = 0.f;
        if (gy >= 0 && gy < HH && gx >= 0 && gx < WW) {
            int gi = ((b*CQK + c)*HH + gy)*WW + gx;
            vq = g_q[gi]; vk = g_k[gi];
        }
        s_qt[idx] = vq; s_kt[idx] = vk;
    }
    for (int idx = tid; idx < 3840; idx += 256) {
        int ch = idx/60, r2 = idx%60, dy = r2/12, xx = r2%12;
        int gy = y + dy - 2, gx = x0 + xx - 2;
        float vv = 0.f;
        if (gy >= 0 && gy < HH && gx >= 0 && gx < WW)
            vv = g_v[((b*CIN + ch)*HH + gy)*WW + gx];
        s_vt[idx] = vv;
    }
    __syncthreads();   // BAR1

    // ---- P1a: q rows -> registers; k rows -> compact smem [25][8] ----
    float q_reg[8];
    {
        float k_reg[8];
#pragma unroll
        for (int cc = 0; cc < 8; cc++) {
            float vq = 0.f, vk = 0.f;
            if (l < 25) {
                int f  = l*8 + cc;
                int ch = f/25, ko = f - ch*25;
                int off = ch*60 + (ko/5)*12 + (ko%5) + p;
                vq = s_qt[off]; vk = s_kt[off];
            }
            q_reg[cc] = vq; k_reg[cc] = vk;
        }
        if (l < 25) {
            float* kr = s_k + p*200 + l*8;
            *(float4*)(kr)     = make_float4(k_reg[0], k_reg[1], k_reg[2], k_reg[3]);
            *(float4*)(kr + 4) = make_float4(k_reg[4], k_reg[5], k_reg[6], k_reg[7]);
        }
    }

    // ---- P1b: expand v tile -> per-pixel interleaved vectors ----
    for (int g = tid; g < 1600; g += 256) {
        int m  = g >> 6, cc = g & 63;
        int ch = g/25,  ko = g - (g/25)*25;
        int off  = ch*60 + (ko/5)*12 + (ko%5);
        int perm = (m>>1)*128 + (m&1)*2 + (cc>>1)*4 + (cc&1);
#pragma unroll
        for (int pp = 0; pp < NPX; pp++) s_vp[pp*VSTRIDE + perm] = s_vt[off + pp];
    }
    __syncthreads();   // BAR2 (halo reads done; T region reusable; k_sm visible)

    // ---- P2: logits via k_sm broadcast + softmax; write DUPLICATED attn ----
    {
        float lg[25];
        const float* ksm = s_k + p*200;
#pragma unroll
        for (int m = 0; m < 25; m++) {
            float4 k0 = *(const float4*)(ksm + m*8);       // broadcast LDS.128
            float4 k1 = *(const float4*)(ksm + m*8 + 4);
            lg[m] = q_reg[0]*k0.x + q_reg[1]*k0.y + q_reg[2]*k0.z + q_reg[3]*k0.w
                  + q_reg[4]*k1.x + q_reg[5]*k1.y + q_reg[6]*k1.z + q_reg[7]*k1.w;
        }
        if (l < 25) {
            float mx = lg[0];
#pragma unroll
            for (int m = 1; m < 25; m++) mx = fmaxf(mx, lg[m]);
            float sum = 0.f;
#pragma unroll
            for (int m = 0; m < 25; m++) { lg[m] = __expf(lg[m] - mx); sum += lg[m]; }
            float inv = 1.0f / sum;
            unsigned long long* row =
                (unsigned long long*)(s_att + p*ADPIX + l*ADSTRIDE);
#pragma unroll
            for (int m = 0; m < 25; m++) {
                float a = lg[m]*inv;
                row[m] = pk2(a, a);          // {a,a} duplicated pair
            }
        }
    }
    __syncthreads();   // BAR3

    // ---- P3a: export attn (deduplicate, coalesced STG) ----
    long pixb = ((long)(b*HH + y))*WW + x0;
    {
        float* ag = attn_out + pixb*625;
        for (int idx = tid; idx < 5000; idx += 256) {
            int pp = idx/625, e = idx - pp*625;
            int n = e/25, m = e - n*25;
            ag[idx] = s_att[pp*ADPIX + n*ADSTRIDE + 2*m];
        }
    }

    // ---- P3b: local = attn @ vp; dup-att LDS.128 + FFMA2, no dup movs ----
    {
        const float* sa = s_att + p*ADPIX;
        const float* vl = s_vp + p*VSTRIDE + 4*l;   // lane covers cc = 2l, 2l+1
        unsigned long long acc[25];
#pragma unroll
        for (int n = 0; n < 25; n++) acc[n] = 0ull;
#pragma unroll
        for (int j = 0; j < 6; j++) {               // m = 4j .. 4j+3
            const unsigned long long* va = (const unsigned long long*)(vl + (2*j)*128);
            const unsigned long long* vb = (const unsigned long long*)(vl + (2*j+1)*128);
            unsigned long long v01 = va[0];   // (m=4j  : c0,c1)
            unsigned long long v23 = va[1];   // (m=4j+1: c0,c1)
            unsigned long long v45 = vb[0];   // (m=4j+2: c0,c1)
            unsigned long long v67 = vb[1];   // (m=4j+3: c0,c1)
#pragma unroll
            for (int n = 0; n < 25; n++) {
                const float* tp = sa + n*ADSTRIDE + 8*j;
                float4 A = *(const float4*)(tp);      // {t0,t0,t1,t1} broadcast
                float4 B = *(const float4*)(tp + 4);  // {t2,t2,t3,t3}
                fma2(acc[n], pk2(A.x, A.y), v01);     // adjacent-pair pack: free
                fma2(acc[n], pk2(A.z, A.w), v23);
                fma2(acc[n], pk2(B.x, B.y), v45);
                fma2(acc[n], pk2(B.z, B.w), v67);
            }
        }
        {   // tail m = 24 (block 12 of the interleaved layout)
            unsigned long long v24 = *(const unsigned long long*)(vl + 1536);
#pragma unroll
            for (int n = 0; n < 25; n++) {
                float2 T = *(const float2*)(sa + n*ADSTRIDE + 48);  // {t,t}
                fma2(acc[n], pk2(T.x, T.y), v24);
            }
        }
        // store chunk (flat layout f = n*64+cc) over own s_vp region
        // (single warp owns this pixel region: program order suffices)
        float* ck = s_vp + p*VSTRIDE;
#pragma unroll
        for (int n = 0; n < 25; n++)
            *(unsigned long long*)(ck + n*64 + 2*l) = acc[n];
    }
    __syncthreads();   // BAR4 (chunks visible; att reads done)

    // ---- P4: in-block fold reduction: chunk -> s_partial[dy][tc][c] ----
    for (int idx = tid; idx < 3840; idx += 256) {
        int nb  = idx/768;
        int rem = idx - nb*768;
        int tc  = rem >> 6;
        int q   = rem & 63;
        int t   = nb*64 + q;
        int c   = t/5;
        int dy  = t - c*5;
        int f0  = 5*t;
        float acc = 0.f;
#pragma unroll
        for (int j = 0; j < 5; j++) {
            int pw = tc - j;
            if (pw >= 0 && pw < 8) acc += s_vp[pw*VSTRIDE + f0 + j];
        }
        s_partial[dy*768 + tc*64 + c] = acc;
    }
    __syncthreads();   // BAR5

    // ---- P5: write fold partials (coalesced float4) ----
    {
        float4* gp = (float4*)(g_partial + (long)blockIdx.x*3840);
        const float4* ps = (const float4*)s_partial;
        for (int idx = tid; idx < 960; idx += 256) gp[idx] = ps[idx];
    }
}

// =====================================================================
// Kernel C: final fold = sum of <=10 partials per output + gamma*() + x
// =====================================================================
__global__ void fold_kernel(const float* __restrict__ x,
                            const float* __restrict__ gamma,
                            float* __restrict__ outp)
{
    int tid = threadIdx.x;
    int c  = tid & 63;
    int xi = tid >> 6;
    int b  = blockIdx.x >> 11;
    int r  = blockIdx.x & 2047;
    int Y  = r >> 4;
    int X  = (r & 15)*8 + xi;

    int xp2   = X + 2;
    int xb_hi = xp2 >> 3;          // tc in [0,8)
    int tc_hi = xp2 - (xb_hi<<3);
    int xb_lo = xb_hi - 1;         // tc in [8,12) if tc_hi < 4
    int tc_lo = tc_hi + 8;

    float acc = 0.f;
#pragma unroll
    for (int dy = 0; dy < 5; dy++) {
        int ys = Y + 2 - dy;
        if (ys < 0 || ys >= HH) continue;
        long rowb = ((long)(b*2048 + ys*16))*3840 + dy*768 + c;
        if (xb_hi < 16)
            acc += g_partial[rowb + (long)xb_hi*3840 + tc_hi*64];
        if (xb_lo >= 0 && tc_lo < 12)
            acc += g_partial[rowb + (long)xb_lo*3840 + tc_lo*64];
    }
    long oidx = (((long)(b*HH + Y))*WW + X)*64 + c;
    outp[oidx] = gamma[0]*acc + x[oidx];
}

// =====================================================================
extern "C" void kernel_launch(void* const* d_in, const int* in_sizes, int n_in,
                              void* d_out, int out_size)
{
    const float* x     = (const float*)d_in[0];
    const float* Wq    = (const float*)d_in[1];
    const float* bq    = (const float*)d_in[2];
    const float* Wk    = (const float*)d_in[3];
    const float* bk    = (const float*)d_in[4];
    const float* Wv    = (const float*)d_in[5];
    const float* bv    = (const float*)d_in[6];
    const float* gamma = (const float*)d_in[7];

    float* outp     = (float*)d_out;
    float* attn_out = outp + (long)BATCH*HH*WW*CIN;   // out first, then attn

    cudaFuncSetAttribute(attn_kernel,
                         cudaFuncAttributeMaxDynamicSharedMemorySize,
                         SMEM_FLOATS*4);

    proj_kernel<<<BATCH*HH/2, 256>>>(x, Wq, bq, Wk, bk, Wv, bv);
    attn_kernel<<<BATCH*HH*(WW/NPX), 256, SMEM_FLOATS*4>>>(attn_out);
    fold_kernel<<<BATCH*HH*(WW/NPX), 512>>>(x, gamma, outp);
}